// round 9
// baseline (speedup 1.0000x reference)
#include <cuda_runtime.h>
#include <cstdint>

#define FEAT 512
#define HID  1024
#define GATES 4096   // 4*HID
#define BATCH 64
#define TLEN  1024
#define NCTA 128
#define CHW  4352    // words per chunk: 64 batch rows x 68 (64 k + 4 pad)
#define CHB  17408   // bytes per chunk

// ---------------- scratch (static device memory; no allocs) ----------------
__device__ float g_xproj[(size_t)TLEN * BATCH * GATES]; // [T][B][4H]  (1 GiB)
__device__ float g_hbuf [(size_t)BATCH * TLEN * HID];   // [B][T][H]   (256 MiB)
// h state, tf32 bits, chunk-blocked padded layout: [16 chunks][64 b][68]
__device__ unsigned g_hbitsA[16 * CHW];
__device__ unsigned g_hbitsB[16 * CHW];
__device__ unsigned g_whpack[(size_t)NCTA * 32 * HID];  // [cta][col32][k] tf32 bits
// per-chunk readiness counters (monotonic): [buffer][chunk]
__device__ unsigned g_ready[2][16];

// ---------------- helpers ----------------
__device__ __forceinline__ unsigned f2tf32(float x) {
    unsigned u;
    asm("cvt.rna.tf32.f32 %0, %1;" : "=r"(u) : "f"(x));
    return u;
}

__device__ __forceinline__ void mma_tf32(float c[4],
                                         unsigned a0, unsigned a1, unsigned a2, unsigned a3,
                                         unsigned b0, unsigned b1) {
    asm volatile(
        "mma.sync.aligned.m16n8k8.row.col.f32.tf32.tf32.f32 "
        "{%0,%1,%2,%3}, {%4,%5,%6,%7}, {%8,%9}, {%0,%1,%2,%3};\n"
        : "+f"(c[0]), "+f"(c[1]), "+f"(c[2]), "+f"(c[3])
        : "r"(a0), "r"(a1), "r"(a2), "r"(a3), "r"(b0), "r"(b1));
}

__device__ __forceinline__ void ldsm_x4(unsigned& r0, unsigned& r1,
                                        unsigned& r2, unsigned& r3, unsigned addr) {
    asm volatile("ldmatrix.sync.aligned.m8n8.x4.shared.b16 {%0,%1,%2,%3}, [%4];"
                 : "=r"(r0), "=r"(r1), "=r"(r2), "=r"(r3) : "r"(addr));
}

__device__ __forceinline__ void ldsm_x2(unsigned& r0, unsigned& r1, unsigned addr) {
    asm volatile("ldmatrix.sync.aligned.m8n8.x2.shared.b16 {%0,%1}, [%2];"
                 : "=r"(r0), "=r"(r1) : "r"(addr));
}

__device__ __forceinline__ float sigmoidf_fast(float x) {
    return 1.0f / (1.0f + __expf(-x));
}

__device__ __forceinline__ void mbar_init(unsigned mbar, unsigned cnt) {
    asm volatile("mbarrier.init.shared.b64 [%0], %1;" :: "r"(mbar), "r"(cnt) : "memory");
}

__device__ __forceinline__ void mbar_expect_tx(unsigned mbar, unsigned bytes) {
    asm volatile("mbarrier.arrive.expect_tx.shared.b64 _, [%0], %1;"
                 :: "r"(mbar), "r"(bytes) : "memory");
}

__device__ __forceinline__ void mbar_wait(unsigned mbar, unsigned phase) {
    asm volatile(
        "{\n\t"
        ".reg .pred P;\n\t"
        "WL_%=: \n\t"
        "mbarrier.try_wait.parity.shared.b64 P, [%0], %1, 0x989680;\n\t"
        "@P bra WD_%=;\n\t"
        "bra WL_%=;\n\t"
        "WD_%=: \n\t"
        "}"
        :: "r"(mbar), "r"(phase) : "memory");
}

__device__ __forceinline__ void bulk_g2s(unsigned dst, const void* src,
                                         unsigned bytes, unsigned mbar) {
    asm volatile(
        "cp.async.bulk.shared::cluster.global.mbarrier::complete_tx::bytes "
        "[%0], [%1], %2, [%3];"
        :: "r"(dst), "l"(src), "r"(bytes), "r"(mbar) : "memory");
}

// spin until g_ready[p][c] >= target (single thread)
__device__ __forceinline__ void wait_chunk(int p, int c, unsigned target) {
    volatile unsigned* a = &g_ready[p][c];
    while (*a < target) { }
}

// ---------------- per-layer prep: pack Wh, zero state, reset counters ------
__global__ void __launch_bounds__(256)
prep_kernel(const float* __restrict__ Wh)
{
    int idx = blockIdx.x * blockDim.x + threadIdx.x;  // 0 .. NCTA*32*HID-1
    if (idx < 32) { g_ready[idx >> 4][idx & 15] = (idx < 16) ? 8u : 0u; }
    if (idx < 16 * CHW) { g_hbitsA[idx] = 0u; }
    int cta = idx >> 15;
    int k   = (idx >> 5) & (HID - 1);
    int c   = idx & 31;
    float v = Wh[(size_t)k * GATES + (c >> 3) * HID + cta * 8 + (c & 7)];
    g_whpack[((size_t)cta << 15) + (size_t)c * HID + k] = f2tf32(v);
}

// ---------------- xproj GEMM: C[m,n] = A[m,:K] @ Wx[:K,n] + bias[n] ----------------
__global__ void __launch_bounds__(256)
xproj_gemm_kernel(const float* __restrict__ Aext, int use_hbuf,
                  const float* __restrict__ Wx, const float* __restrict__ bias, int K)
{
    const float* A = use_hbuf ? g_hbuf : Aext;

    __shared__ unsigned As[128][36];
    __shared__ unsigned Bs[32][136];

    const int bm = blockIdx.y, bn = blockIdx.x;
    const int tid = threadIdx.x;
    const int wid = tid >> 5, lane = tid & 31;
    const int wm = (wid >> 2) * 64;
    const int wn = (wid & 3) * 32;
    const int group = lane >> 2, tid4 = lane & 3;

    float acc[4][4][4];
#pragma unroll
    for (int i = 0; i < 4; i++)
#pragma unroll
        for (int j = 0; j < 4; j++)
#pragma unroll
            for (int k = 0; k < 4; k++) acc[i][j][k] = 0.0f;

    const float* Aptr = A + (size_t)(bm * 128) * K;
    const float* Bptr = Wx + (size_t)bn * 128;

    for (int k0 = 0; k0 < K; k0 += 32) {
#pragma unroll
        for (int j = 0; j < 4; j++) {
            int idx = tid + j * 256;
            int r = idx >> 3, c4 = idx & 7;
            float4 v = *(const float4*)(Aptr + (size_t)r * K + k0 + c4 * 4);
            As[r][c4 * 4 + 0] = f2tf32(v.x);
            As[r][c4 * 4 + 1] = f2tf32(v.y);
            As[r][c4 * 4 + 2] = f2tf32(v.z);
            As[r][c4 * 4 + 3] = f2tf32(v.w);
        }
#pragma unroll
        for (int j = 0; j < 4; j++) {
            int idx = tid + j * 256;
            int r = idx >> 5, c4 = idx & 31;
            float4 v = *(const float4*)(Bptr + (size_t)(k0 + r) * GATES + c4 * 4);
            Bs[r][c4 * 4 + 0] = f2tf32(v.x);
            Bs[r][c4 * 4 + 1] = f2tf32(v.y);
            Bs[r][c4 * 4 + 2] = f2tf32(v.z);
            Bs[r][c4 * 4 + 3] = f2tf32(v.w);
        }
        __syncthreads();

#pragma unroll
        for (int kk = 0; kk < 32; kk += 8) {
            unsigned a[4][4], b[4][2];
#pragma unroll
            for (int mf = 0; mf < 4; mf++) {
                int m = wm + mf * 16;
                a[mf][0] = As[m + group][kk + tid4];
                a[mf][1] = As[m + 8 + group][kk + tid4];
                a[mf][2] = As[m + group][kk + 4 + tid4];
                a[mf][3] = As[m + 8 + group][kk + 4 + tid4];
            }
#pragma unroll
            for (int nf = 0; nf < 4; nf++) {
                int n = wn + nf * 8;
                b[nf][0] = Bs[kk + tid4][n + group];
                b[nf][1] = Bs[kk + 4 + tid4][n + group];
            }
#pragma unroll
            for (int mf = 0; mf < 4; mf++)
#pragma unroll
                for (int nf = 0; nf < 4; nf++)
                    mma_tf32(acc[mf][nf], a[mf][0], a[mf][1], a[mf][2], a[mf][3],
                             b[nf][0], b[nf][1]);
        }
        __syncthreads();
    }

#pragma unroll
    for (int mf = 0; mf < 4; mf++) {
#pragma unroll
        for (int nf = 0; nf < 4; nf++) {
            int col = bn * 128 + wn + nf * 8 + 2 * tid4;
            float bv0 = bias[col], bv1 = bias[col + 1];
#pragma unroll
            for (int r = 0; r < 2; r++) {
                int m = bm * 128 + wm + mf * 16 + group + r * 8;
                int bidx = m >> 10;
                int tt = m & (TLEN - 1);
                float2 v;
                v.x = acc[mf][nf][2 * r + 0] + bv0;
                v.y = acc[mf][nf][2 * r + 1] + bv1;
                *(float2*)&g_xproj[((size_t)tt * BATCH + bidx) * GATES + col] = v;
            }
        }
    }
}

// ---------------- persistent LSTM layer kernel ----------------
// 128 CTAs x 256 threads. CTA owns hidden units [j0, j0+8) (32 gate cols).
// Wh slice resident in smem. h staged via TMA bulk copies, double buffered.
// Cross-CTA sync: per-chunk monotonic readiness counters (no lump barrier).
struct LayerSmem {
    unsigned Bs[32][1028];        // resident Wh slice  [col][k]  (131,584 B)
    unsigned As[2][2][64][68];    // [buf][khalf][b][k] staging   ( 69,632 B)
    float zsm[2][4][64][9];       // [khalf][gate][b][jj]         ( 18,432 B)
    unsigned long long mbar[2];   // TMA completion barriers
};

__global__ void __launch_bounds__(256, 1)
lstm_layer_kernel(float* __restrict__ dout_ext, int last)
{
    extern __shared__ char dynbuf[];
    LayerSmem& sm = *reinterpret_cast<LayerSmem*>(dynbuf);

    float* dout = last ? dout_ext : g_hbuf;
    const int tid = threadIdx.x;
    const int wid = tid >> 5, lane = tid & 31;
    const int g = wid & 3;            // gate
    const int hl_w = wid >> 2;        // K-half
    const int j0 = blockIdx.x * 8;
    const int group = lane >> 2, tid4 = lane & 3;
    const unsigned* wp = g_whpack + ((size_t)blockIdx.x << 15);  // [32][1024]

    const unsigned mb0 = (unsigned)__cvta_generic_to_shared(&sm.mbar[0]);
    const unsigned mb1 = (unsigned)__cvta_generic_to_shared(&sm.mbar[1]);
    const unsigned asbase = (unsigned)__cvta_generic_to_shared(&sm.As[0][0][0][0]);
    const unsigned bsbase = (unsigned)__cvta_generic_to_shared(&sm.Bs[0][0]);

    // ldmatrix per-lane addresses:
    const unsigned aoff = (((lane & 15) * 68 + ((lane >> 4) << 2)) << 2);
    const unsigned abase0 = asbase + (unsigned)(hl_w * CHB) + aoff;           // buf 0
    const unsigned abase1 = asbase + (unsigned)(2 * CHB + hl_w * CHB) + aoff; // buf 1
    const unsigned bbase = bsbase +
        ((unsigned)((g * 8 + (lane & 7)) * 1028 + hl_w * 512 + (((lane >> 3) & 1) << 2)) << 2);

    if (tid == 0) {
        mbar_init(mb0, 1);
        mbar_init(mb1, 1);
        asm volatile("fence.proxy.async.shared::cta;" ::: "memory");
    }

    // ---- load resident Wh slice once: 32 cols x 1024 k ----
#pragma unroll
    for (int j = 0; j < 32; ++j) {
        int idx = tid + j * 256;      // 0..8191 uint4s
        int c = idx >> 8;
        int k4 = idx & 255;
        uint4 v = *(const uint4*)(wp + (size_t)c * HID + k4 * 4);
        *(uint4*)&sm.Bs[c][k4 * 4] = v;
    }

    // cell state in registers: thread handles (b,jj) pairs idx=tid, tid+256
    float creg[2] = {0.0f, 0.0f};
    unsigned ph0 = 0, ph1 = 0;
    const int hchunk = j0 >> 6;       // chunk this CTA's h columns live in

    __syncthreads();

    for (int t = 0; t < TLEN; ++t) {
        const int hb = t & 1;                       // input buffer parity
        const unsigned* hprev = hb ? g_hbitsB : g_hbitsA;
        unsigned* hnext = hb ? g_hbitsA : g_hbitsB;
        const unsigned tgt = 8u * ((unsigned)(t >> 1) + 1u);  // readiness target

        // prefetch xproj for this step's epilogue (hides DRAM latency)
        const float* xp = g_xproj + (size_t)t * BATCH * GATES;
        float xpv[2][4];
#pragma unroll
        for (int e = 0; e < 2; ++e) {
            int idx = tid + e * 256;
            int b = idx >> 3, jj = idx & 7;
            const float* xpb = xp + (size_t)b * GATES + j0 + jj;
#pragma unroll
            for (int gg = 0; gg < 4; ++gg) xpv[e][gg] = __ldg(xpb + gg * HID);
        }

        // stage chunk pair (0, 8) into buf 0 once both are ready
        if (tid == 0) {
            wait_chunk(hb, 0, tgt);
            wait_chunk(hb, 8, tgt);
            __threadfence();
            mbar_expect_tx(mb0, 2 * CHB);
            bulk_g2s(asbase, hprev, CHB, mb0);
            bulk_g2s(asbase + CHB, hprev + 8 * CHW, CHB, mb0);
        }

        float acc[4][4];
#pragma unroll
        for (int i = 0; i < 4; i++)
#pragma unroll
            for (int k = 0; k < 4; k++) acc[i][k] = 0.0f;

#pragma unroll 1
        for (int i = 0; i < 8; ++i) {
            const int buf = i & 1;
            // wait for this buffer's TMA completion
            if (buf == 0) { mbar_wait(mb0, ph0); ph0 ^= 1; }
            else          { mbar_wait(mb1, ph1); ph1 ^= 1; }

            // issue next chunk pair into the other buffer
            if (tid == 0 && i < 7) {
                const int nb = (i + 1) & 1;
                const unsigned m = nb ? mb1 : mb0;
                const unsigned d = asbase + (unsigned)nb * (2 * CHB);
                wait_chunk(hb, i + 1, tgt);
                wait_chunk(hb, i + 9, tgt);
                __threadfence();
                mbar_expect_tx(m, 2 * CHB);
                bulk_g2s(d, hprev + (size_t)(i + 1) * CHW, CHB, m);
                bulk_g2s(d + CHB, hprev + (size_t)(9 + i) * CHW, CHB, m);
            }

            const unsigned ab = buf ? abase1 : abase0;
            const int kb = i * 64;  // k offset within the 512-half
#pragma unroll
            for (int kk = 0; kk < 64; kk += 8) {
                unsigned b0, b1;
                ldsm_x2(b0, b1, bbase + (unsigned)((kb + kk) << 2));
#pragma unroll
                for (int mf = 0; mf < 4; ++mf) {
                    unsigned a0, a1, a2, a3;
                    ldsm_x4(a0, a1, a2, a3, ab + (unsigned)((mf * 1088 + kk) << 2));
                    mma_tf32(acc[mf], a0, a1, a2, a3, b0, b1);
                }
            }
            __syncthreads();  // mma on buf done -> buf free for next TMA
        }

        // stash z fragments
#pragma unroll
        for (int mf = 0; mf < 4; ++mf) {
            int m = mf * 16 + group, n = 2 * tid4;
            sm.zsm[hl_w][g][m][n]     = acc[mf][0];
            sm.zsm[hl_w][g][m][n + 1] = acc[mf][1];
            sm.zsm[hl_w][g][m + 8][n]     = acc[mf][2];
            sm.zsm[hl_w][g][m + 8][n + 1] = acc[mf][3];
        }
        __syncthreads();

        // elementwise gates: 64 b x 8 jj = 512 / 256 thr = 2 each; c in regs
#pragma unroll
        for (int e = 0; e < 2; ++e) {
            int idx = tid + e * 256;
            int b = idx >> 3, jj = idx & 7;
            int col = j0 + jj;
            float zi = sm.zsm[0][0][b][jj] + sm.zsm[1][0][b][jj] + xpv[e][0];
            float zf = sm.zsm[0][1][b][jj] + sm.zsm[1][1][b][jj] + xpv[e][1];
            float zg = sm.zsm[0][2][b][jj] + sm.zsm[1][2][b][jj] + xpv[e][2];
            float zo = sm.zsm[0][3][b][jj] + sm.zsm[1][3][b][jj] + xpv[e][3];
            float i_ = sigmoidf_fast(zi);
            float f_ = sigmoidf_fast(zf);
            float gg_ = tanhf(zg);
            float o_ = sigmoidf_fast(zo);
            float c_ = f_ * creg[e] + i_ * gg_;
            creg[e] = c_;
            float h_ = o_ * tanhf(c_);
            hnext[hchunk * CHW + b * 68 + (col & 63)] = f2tf32(h_);
            dout[(size_t)b * TLEN * HID + (size_t)t * HID + col] = h_;
        }
        __syncthreads();  // all h stores for this CTA's chunk done

        // ---- distributed arrival: publish this CTA's chunk of hnext ----
        if (tid == 0) {
            asm volatile("fence.proxy.async;" ::: "memory");
            __threadfence();
            atomicAdd(&g_ready[(t + 1) & 1][hchunk], 1u);
        }
        // no global wait here — next step's chunk polls provide backpressure
    }
}

// ---------------- launch ----------------
extern "C" void kernel_launch(void* const* d_in, const int* in_sizes, int n_in,
                              void* d_out, int out_size)
{
    (void)in_sizes; (void)n_in; (void)out_size;
    const float* xs = (const float*)d_in[0];
    const float* Wx[3] = {(const float*)d_in[1], (const float*)d_in[4], (const float*)d_in[7]};
    const float* Wh[3] = {(const float*)d_in[2], (const float*)d_in[5], (const float*)d_in[8]};
    const float* bb[3] = {(const float*)d_in[3], (const float*)d_in[6], (const float*)d_in[9]};
    float* out = (float*)d_out;

    static int smem_set = 0;
    int smem_bytes = (int)sizeof(LayerSmem);
    if (!smem_set) {
        cudaFuncSetAttribute(lstm_layer_kernel,
                             cudaFuncAttributeMaxDynamicSharedMemorySize, smem_bytes);
        smem_set = 1;
    }

    for (int l = 0; l < 3; l++) {
        int K = (l == 0) ? FEAT : HID;
        prep_kernel<<<(NCTA * 32 * HID) / 256, 256>>>(Wh[l]);
        dim3 ggrid(GATES / 128, (BATCH * TLEN) / 128);
        xproj_gemm_kernel<<<ggrid, 256>>>(l == 0 ? xs : nullptr, l > 0 ? 1 : 0,
                                          Wx[l], bb[l], K);
        lstm_layer_kernel<<<NCTA, 256, smem_bytes>>>(out, (l == 2) ? 1 : 0);
    }
}

// round 16
// speedup vs baseline: 1.7199x; 1.7199x over previous
#include <cuda_runtime.h>
#include <cuda_fp16.h>
#include <cstdint>

#define FEAT 512
#define HID  1024
#define GATES 4096   // 4*HID
#define BATCH 64
#define TLEN  1024
#define NCTA 128
#define CHWH 4608    // halves per chunk: 64 batch rows x 72 (64 k + 8 pad)
#define CHB  9216    // bytes per chunk

// ---------------- scratch (static device memory; no allocs) ----------------
__device__ float g_xproj[(size_t)TLEN * BATCH * GATES]; // [T][B][4H]  (1 GiB)
__device__ float g_hbuf [(size_t)BATCH * TLEN * HID];   // [B][T][H]   (256 MiB)
// h state, fp16, chunk-blocked padded layout: [16 chunks][64 b][72]
__device__ __half g_hbitsA[16 * CHWH];
__device__ __half g_hbitsB[16 * CHWH];
__device__ __half g_whpack[(size_t)NCTA * 32 * HID];    // [cta][col32][k] fp16
__device__ unsigned g_bar_count;
__device__ unsigned g_bar_epoch;

// ---------------- helpers ----------------
__device__ __forceinline__ unsigned f2tf32(float x) {
    unsigned u;
    asm("cvt.rna.tf32.f32 %0, %1;" : "=r"(u) : "f"(x));
    return u;
}

__device__ __forceinline__ void mma_tf32(float c[4],
                                         unsigned a0, unsigned a1, unsigned a2, unsigned a3,
                                         unsigned b0, unsigned b1) {
    asm volatile(
        "mma.sync.aligned.m16n8k8.row.col.f32.tf32.tf32.f32 "
        "{%0,%1,%2,%3}, {%4,%5,%6,%7}, {%8,%9}, {%0,%1,%2,%3};\n"
        : "+f"(c[0]), "+f"(c[1]), "+f"(c[2]), "+f"(c[3])
        : "r"(a0), "r"(a1), "r"(a2), "r"(a3), "r"(b0), "r"(b1));
}

__device__ __forceinline__ void mma_f16(float c[4],
                                        unsigned a0, unsigned a1, unsigned a2, unsigned a3,
                                        unsigned b0, unsigned b1) {
    asm volatile(
        "mma.sync.aligned.m16n8k16.row.col.f32.f16.f16.f32 "
        "{%0,%1,%2,%3}, {%4,%5,%6,%7}, {%8,%9}, {%0,%1,%2,%3};\n"
        : "+f"(c[0]), "+f"(c[1]), "+f"(c[2]), "+f"(c[3])
        : "r"(a0), "r"(a1), "r"(a2), "r"(a3), "r"(b0), "r"(b1));
}

__device__ __forceinline__ void ldsm_x4(unsigned& r0, unsigned& r1,
                                        unsigned& r2, unsigned& r3, unsigned addr) {
    asm volatile("ldmatrix.sync.aligned.m8n8.x4.shared.b16 {%0,%1,%2,%3}, [%4];"
                 : "=r"(r0), "=r"(r1), "=r"(r2), "=r"(r3) : "r"(addr));
}

__device__ __forceinline__ void ldsm_x2(unsigned& r0, unsigned& r1, unsigned addr) {
    asm volatile("ldmatrix.sync.aligned.m8n8.x2.shared.b16 {%0,%1}, [%2];"
                 : "=r"(r0), "=r"(r1) : "r"(addr));
}

__device__ __forceinline__ float sigmoidf_fast(float x) {
    return 1.0f / (1.0f + __expf(-x));
}

__device__ __forceinline__ void mbar_init(unsigned mbar, unsigned cnt) {
    asm volatile("mbarrier.init.shared.b64 [%0], %1;" :: "r"(mbar), "r"(cnt) : "memory");
}

__device__ __forceinline__ void mbar_expect_tx(unsigned mbar, unsigned bytes) {
    asm volatile("mbarrier.arrive.expect_tx.shared.b64 _, [%0], %1;"
                 :: "r"(mbar), "r"(bytes) : "memory");
}

__device__ __forceinline__ void mbar_wait(unsigned mbar, unsigned phase) {
    asm volatile(
        "{\n\t"
        ".reg .pred P;\n\t"
        "WL_%=: \n\t"
        "mbarrier.try_wait.parity.shared.b64 P, [%0], %1, 0x989680;\n\t"
        "@P bra WD_%=;\n\t"
        "bra WL_%=;\n\t"
        "WD_%=: \n\t"
        "}"
        :: "r"(mbar), "r"(phase) : "memory");
}

__device__ __forceinline__ void bulk_g2s(unsigned dst, const void* src,
                                         unsigned bytes, unsigned mbar) {
    asm volatile(
        "cp.async.bulk.shared::cluster.global.mbarrier::complete_tx::bytes "
        "[%0], [%1], %2, [%3];"
        :: "r"(dst), "l"(src), "r"(bytes), "r"(mbar) : "memory");
}

// ---------------- per-layer prep: pack Wh (fp16), zero state, reset barrier -
__global__ void __launch_bounds__(256)
prep_kernel(const float* __restrict__ Wh)
{
    int idx = blockIdx.x * blockDim.x + threadIdx.x;  // 0 .. NCTA*32*HID-1
    if (idx == 0) { g_bar_count = 0; g_bar_epoch = 0; }
    if (idx < (16 * CHWH) / 2) { ((unsigned*)g_hbitsA)[idx] = 0u; }
    int cta = idx >> 15;
    int k   = (idx >> 5) & (HID - 1);
    int c   = idx & 31;
    float v = Wh[(size_t)k * GATES + (c >> 3) * HID + cta * 8 + (c & 7)];
    g_whpack[((size_t)cta << 15) + (size_t)c * HID + k] = __float2half_rn(v);
}

// ---------------- xproj GEMM (tf32, unchanged): C = A @ Wx + bias ----------
__global__ void __launch_bounds__(256)
xproj_gemm_kernel(const float* __restrict__ Aext, int use_hbuf,
                  const float* __restrict__ Wx, const float* __restrict__ bias, int K)
{
    const float* A = use_hbuf ? g_hbuf : Aext;

    __shared__ unsigned As[128][36];
    __shared__ unsigned Bs[32][136];

    const int bm = blockIdx.y, bn = blockIdx.x;
    const int tid = threadIdx.x;
    const int wid = tid >> 5, lane = tid & 31;
    const int wm = (wid >> 2) * 64;
    const int wn = (wid & 3) * 32;
    const int group = lane >> 2, tid4 = lane & 3;

    float acc[4][4][4];
#pragma unroll
    for (int i = 0; i < 4; i++)
#pragma unroll
        for (int j = 0; j < 4; j++)
#pragma unroll
            for (int k = 0; k < 4; k++) acc[i][j][k] = 0.0f;

    const float* Aptr = A + (size_t)(bm * 128) * K;
    const float* Bptr = Wx + (size_t)bn * 128;

    for (int k0 = 0; k0 < K; k0 += 32) {
#pragma unroll
        for (int j = 0; j < 4; j++) {
            int idx = tid + j * 256;
            int r = idx >> 3, c4 = idx & 7;
            float4 v = *(const float4*)(Aptr + (size_t)r * K + k0 + c4 * 4);
            As[r][c4 * 4 + 0] = f2tf32(v.x);
            As[r][c4 * 4 + 1] = f2tf32(v.y);
            As[r][c4 * 4 + 2] = f2tf32(v.z);
            As[r][c4 * 4 + 3] = f2tf32(v.w);
        }
#pragma unroll
        for (int j = 0; j < 4; j++) {
            int idx = tid + j * 256;
            int r = idx >> 5, c4 = idx & 31;
            float4 v = *(const float4*)(Bptr + (size_t)(k0 + r) * GATES + c4 * 4);
            Bs[r][c4 * 4 + 0] = f2tf32(v.x);
            Bs[r][c4 * 4 + 1] = f2tf32(v.y);
            Bs[r][c4 * 4 + 2] = f2tf32(v.z);
            Bs[r][c4 * 4 + 3] = f2tf32(v.w);
        }
        __syncthreads();

#pragma unroll
        for (int kk = 0; kk < 32; kk += 8) {
            unsigned a[4][4], b[4][2];
#pragma unroll
            for (int mf = 0; mf < 4; mf++) {
                int m = wm + mf * 16;
                a[mf][0] = As[m + group][kk + tid4];
                a[mf][1] = As[m + 8 + group][kk + tid4];
                a[mf][2] = As[m + group][kk + 4 + tid4];
                a[mf][3] = As[m + 8 + group][kk + 4 + tid4];
            }
#pragma unroll
            for (int nf = 0; nf < 4; nf++) {
                int n = wn + nf * 8;
                b[nf][0] = Bs[kk + tid4][n + group];
                b[nf][1] = Bs[kk + 4 + tid4][n + group];
            }
#pragma unroll
            for (int mf = 0; mf < 4; mf++)
#pragma unroll
                for (int nf = 0; nf < 4; nf++)
                    mma_tf32(acc[mf][nf], a[mf][0], a[mf][1], a[mf][2], a[mf][3],
                             b[nf][0], b[nf][1]);
        }
        __syncthreads();
    }

#pragma unroll
    for (int mf = 0; mf < 4; mf++) {
#pragma unroll
        for (int nf = 0; nf < 4; nf++) {
            int col = bn * 128 + wn + nf * 8 + 2 * tid4;
            float bv0 = bias[col], bv1 = bias[col + 1];
#pragma unroll
            for (int r = 0; r < 2; r++) {
                int m = bm * 128 + wm + mf * 16 + group + r * 8;
                int bidx = m >> 10;
                int tt = m & (TLEN - 1);
                float2 v;
                v.x = acc[mf][nf][2 * r + 0] + bv0;
                v.y = acc[mf][nf][2 * r + 1] + bv1;
                *(float2*)&g_xproj[((size_t)tt * BATCH + bidx) * GATES + col] = v;
            }
        }
    }
}

// ---------------- persistent LSTM layer kernel (fp16 recurrence GEMM) ------
// 128 CTAs x 256 threads. CTA owns hidden units [j0, j0+8) (32 gate cols).
// Wh slice resident in smem (fp16). h staged via TMA bulk copies, double
// buffered. ldmatrix fragments, m16n8k16 f16 mma, fp32 accum. c in registers.
struct LayerSmem {
    __half Bs[32][1032];          // resident Wh slice [col][k]   (66,048 B)
    __half As[2][2][64][72];      // [buf][khalf][b][k] staging   (36,864 B)
    float zsm[2][4][64][9];       // [khalf][gate][b][jj]         (18,432 B)
    unsigned long long mbar[2];   // TMA completion barriers
};

__global__ void __launch_bounds__(256, 1)
lstm_layer_kernel(float* __restrict__ dout_ext, int last)
{
    extern __shared__ char dynbuf[];
    LayerSmem& sm = *reinterpret_cast<LayerSmem*>(dynbuf);

    float* dout = last ? dout_ext : g_hbuf;
    const int tid = threadIdx.x;
    const int wid = tid >> 5, lane = tid & 31;
    const int g = wid & 3;            // gate
    const int hl_w = wid >> 2;        // K-half (0: k<512, 1: k>=512)
    const int j0 = blockIdx.x * 8;
    const int group = lane >> 2, tid4 = lane & 3;
    const __half* wp = g_whpack + ((size_t)blockIdx.x << 15);  // [32][1024] halves

    const unsigned mb0 = (unsigned)__cvta_generic_to_shared(&sm.mbar[0]);
    const unsigned mb1 = (unsigned)__cvta_generic_to_shared(&sm.mbar[1]);
    const unsigned asbase = (unsigned)__cvta_generic_to_shared(&sm.As[0][0][0][0]);
    const unsigned bsbase = (unsigned)__cvta_generic_to_shared(&sm.Bs[0][0]);

    // ldmatrix per-lane addresses (byte offsets):
    // A: row = lane&15 (stride 144B), k-octet select = lane>>4 (+16B)
    const unsigned aoff = (lane & 15) * 144u + ((lane >> 4) << 4);
    const unsigned abase0 = asbase + (unsigned)(hl_w * CHB) + aoff;           // buf 0
    const unsigned abase1 = abase0 + 2u * CHB;                                 // buf 1
    // B: row = g*8 + (lane&7) (stride 2064B), khalf offset 1024B, k-octet (lane>>3)&1
    const unsigned bbase = bsbase + (unsigned)((g * 8 + (lane & 7)) * 2064)
                           + (unsigned)(hl_w * 1024) + ((((unsigned)lane >> 3) & 1u) << 4);

    if (tid == 0) {
        mbar_init(mb0, 1);
        mbar_init(mb1, 1);
        asm volatile("fence.proxy.async.shared::cta;" ::: "memory");
    }

    // ---- load resident Wh slice once: 32 cols x 1024 k halves ----
#pragma unroll
    for (int j = 0; j < 16; ++j) {
        int idx = tid + j * 256;      // 0..4095 uint4s (16B = 8 halves)
        int c = idx >> 7;
        int k16 = idx & 127;
        uint4 v = *(const uint4*)((const char*)(wp + (size_t)c * HID) + k16 * 16);
        *(uint4*)((char*)&sm.Bs[c][0] + k16 * 16) = v;
    }

    // cell state in registers: thread handles (b,jj) pairs idx=tid, tid+256
    float creg[2] = {0.0f, 0.0f};
    unsigned ph0 = 0, ph1 = 0;

    __syncthreads();

    for (int t = 0; t < TLEN; ++t) {
        const __half* hprev = (t & 1) ? g_hbitsB : g_hbitsA;
        __half* hnext = (t & 1) ? g_hbitsA : g_hbitsB;

        // prefetch xproj for this step's epilogue (hides DRAM latency)
        const float* xp = g_xproj + (size_t)t * BATCH * GATES;
        float xpv[2][4];
#pragma unroll
        for (int e = 0; e < 2; ++e) {
            int idx = tid + e * 256;
            int b = idx >> 3, jj = idx & 7;
            const float* xpb = xp + (size_t)b * GATES + j0 + jj;
#pragma unroll
            for (int gg = 0; gg < 4; ++gg) xpv[e][gg] = __ldg(xpb + gg * HID);
        }

        // stage chunk pair (0, 8) into buf 0
        if (tid == 0) {
            mbar_expect_tx(mb0, 2 * CHB);
            bulk_g2s(asbase, hprev, CHB, mb0);
            bulk_g2s(asbase + CHB, hprev + 8 * CHWH, CHB, mb0);
        }

        float acc[4][4];
#pragma unroll
        for (int i = 0; i < 4; i++)
#pragma unroll
            for (int k = 0; k < 4; k++) acc[i][k] = 0.0f;

#pragma unroll 1
        for (int i = 0; i < 8; ++i) {
            const int buf = i & 1;
            // wait for this buffer's TMA completion
            if (buf == 0) { mbar_wait(mb0, ph0); ph0 ^= 1; }
            else          { mbar_wait(mb1, ph1); ph1 ^= 1; }

            // issue next chunk pair into the other buffer
            if (tid == 0 && i < 7) {
                const int nb = (i + 1) & 1;
                const unsigned m = nb ? mb1 : mb0;
                const unsigned d = asbase + (unsigned)nb * (2 * CHB);
                mbar_expect_tx(m, 2 * CHB);
                bulk_g2s(d, hprev + (size_t)(i + 1) * CHWH, CHB, m);          // half0
                bulk_g2s(d + CHB, hprev + (size_t)(9 + i) * CHWH, CHB, m);    // half1
            }

            const unsigned ab = buf ? abase1 : abase0;
            const unsigned kglob = (unsigned)i * 128u;  // B k-offset (bytes)
#pragma unroll
            for (int kk = 0; kk < 4; ++kk) {            // 4 x k16 per chunk
                const unsigned kc = (unsigned)kk * 32u; // within-chunk (A) offset
                unsigned b0, b1;
                ldsm_x2(b0, b1, bbase + kglob + kc);    // B: global k
#pragma unroll
                for (int mf = 0; mf < 4; ++mf) {
                    unsigned a0, a1, a2, a3;
                    ldsm_x4(a0, a1, a2, a3, ab + (unsigned)mf * 2304u + kc);  // A: chunk k
                    mma_f16(acc[mf], a0, a1, a2, a3, b0, b1);
                }
            }
            __syncthreads();  // mma on buf done -> buf free for next TMA
        }

        // stash z fragments
#pragma unroll
        for (int mf = 0; mf < 4; ++mf) {
            int m = mf * 16 + group, n = 2 * tid4;
            sm.zsm[hl_w][g][m][n]     = acc[mf][0];
            sm.zsm[hl_w][g][m][n + 1] = acc[mf][1];
            sm.zsm[hl_w][g][m + 8][n]     = acc[mf][2];
            sm.zsm[hl_w][g][m + 8][n + 1] = acc[mf][3];
        }
        __syncthreads();

        // elementwise gates: 64 b x 8 jj = 512 / 256 thr = 2 each; c in regs
        const int hchunk = j0 >> 6;           // this CTA's cols live in one chunk
#pragma unroll
        for (int e = 0; e < 2; ++e) {
            int idx = tid + e * 256;
            int b = idx >> 3, jj = idx & 7;
            int col = j0 + jj;
            float zi = sm.zsm[0][0][b][jj] + sm.zsm[1][0][b][jj] + xpv[e][0];
            float zf = sm.zsm[0][1][b][jj] + sm.zsm[1][1][b][jj] + xpv[e][1];
            float zg = sm.zsm[0][2][b][jj] + sm.zsm[1][2][b][jj] + xpv[e][2];
            float zo = sm.zsm[0][3][b][jj] + sm.zsm[1][3][b][jj] + xpv[e][3];
            float i_ = sigmoidf_fast(zi);
            float f_ = sigmoidf_fast(zf);
            float gg_ = tanhf(zg);
            float o_ = sigmoidf_fast(zo);
            float c_ = f_ * creg[e] + i_ * gg_;
            creg[e] = c_;
            float h_ = o_ * tanhf(c_);
            hnext[hchunk * CHWH + b * 72 + (col & 63)] = __float2half_rn(h_);
            dout[(size_t)b * TLEN * HID + (size_t)t * HID + col] = h_;
        }
        __syncthreads();

        // ---- grid barrier (monotonic epoch) ----
        if (tid == 0) {
            asm volatile("fence.proxy.async;" ::: "memory");
            __threadfence();
            unsigned prev = atomicAdd(&g_bar_count, 1u);
            if (prev == NCTA - 1) {
                g_bar_count = 0;
                __threadfence();
                atomicExch(&g_bar_epoch, (unsigned)(t + 1));
            } else {
                volatile unsigned* ep = &g_bar_epoch;
                while (*ep < (unsigned)(t + 1)) { }
                __threadfence();
            }
        }
        __syncthreads();
    }
}

// ---------------- launch ----------------
extern "C" void kernel_launch(void* const* d_in, const int* in_sizes, int n_in,
                              void* d_out, int out_size)
{
    (void)in_sizes; (void)n_in; (void)out_size;
    const float* xs = (const float*)d_in[0];
    const float* Wx[3] = {(const float*)d_in[1], (const float*)d_in[4], (const float*)d_in[7]};
    const float* Wh[3] = {(const float*)d_in[2], (const float*)d_in[5], (const float*)d_in[8]};
    const float* bb[3] = {(const float*)d_in[3], (const float*)d_in[6], (const float*)d_in[9]};
    float* out = (float*)d_out;

    static int smem_set = 0;
    int smem_bytes = (int)sizeof(LayerSmem);
    if (!smem_set) {
        cudaFuncSetAttribute(lstm_layer_kernel,
                             cudaFuncAttributeMaxDynamicSharedMemorySize, smem_bytes);
        smem_set = 1;
    }

    for (int l = 0; l < 3; l++) {
        int K = (l == 0) ? FEAT : HID;
        prep_kernel<<<(NCTA * 32 * HID) / 256, 256>>>(Wh[l]);
        dim3 ggrid(GATES / 128, (BATCH * TLEN) / 128);
        xproj_gemm_kernel<<<ggrid, 256>>>(l == 0 ? xs : nullptr, l > 0 ? 1 : 0,
                                          Wx[l], bb[l], K);
        lstm_layer_kernel<<<NCTA, 256, smem_bytes>>>(out, (l == 2) ? 1 : 0);
    }
}

// round 17
// speedup vs baseline: 1.9503x; 1.1339x over previous
#include <cuda_runtime.h>
#include <cuda_fp16.h>
#include <cstdint>

#define FEAT 512
#define HID  1024
#define GATES 4096   // 4*HID
#define BATCH 64
#define TLEN  1024
#define NCTA 128
#define CHWH 4608    // halves per chunk: 64 batch rows x 72 (64 k + 8 pad)
#define CHB  9216    // bytes per chunk

// ---------------- scratch (static device memory; no allocs) ----------------
__device__ float g_xproj[(size_t)TLEN * BATCH * GATES]; // [T][B][4H]  (1 GiB)
__device__ float g_hbuf [(size_t)BATCH * TLEN * HID];   // [B][T][H]   (256 MiB)
// h state, fp16, chunk-blocked padded layout: [16 chunks][64 b][72]
__device__ __half g_hbitsA[16 * CHWH];
__device__ __half g_hbitsB[16 * CHWH];
__device__ __half g_whpack[(size_t)NCTA * 32 * HID];    // [cta][col32][k] fp16
__device__ unsigned g_bar_count;
__device__ unsigned g_bar_epoch;

// ---------------- helpers ----------------
__device__ __forceinline__ void mma_f16(float c[4],
                                        unsigned a0, unsigned a1, unsigned a2, unsigned a3,
                                        unsigned b0, unsigned b1) {
    asm volatile(
        "mma.sync.aligned.m16n8k16.row.col.f32.f16.f16.f32 "
        "{%0,%1,%2,%3}, {%4,%5,%6,%7}, {%8,%9}, {%0,%1,%2,%3};\n"
        : "+f"(c[0]), "+f"(c[1]), "+f"(c[2]), "+f"(c[3])
        : "r"(a0), "r"(a1), "r"(a2), "r"(a3), "r"(b0), "r"(b1));
}

__device__ __forceinline__ void ldsm_x4(unsigned& r0, unsigned& r1,
                                        unsigned& r2, unsigned& r3, unsigned addr) {
    asm volatile("ldmatrix.sync.aligned.m8n8.x4.shared.b16 {%0,%1,%2,%3}, [%4];"
                 : "=r"(r0), "=r"(r1), "=r"(r2), "=r"(r3) : "r"(addr));
}

__device__ __forceinline__ void ldsm_x2(unsigned& r0, unsigned& r1, unsigned addr) {
    asm volatile("ldmatrix.sync.aligned.m8n8.x2.shared.b16 {%0,%1}, [%2];"
                 : "=r"(r0), "=r"(r1) : "r"(addr));
}

__device__ __forceinline__ void ldsm_x2t(unsigned& r0, unsigned& r1, unsigned addr) {
    asm volatile("ldmatrix.sync.aligned.m8n8.x2.trans.shared.b16 {%0,%1}, [%2];"
                 : "=r"(r0), "=r"(r1) : "r"(addr));
}

__device__ __forceinline__ float sigmoidf_fast(float x) {
    return 1.0f / (1.0f + __expf(-x));
}

__device__ __forceinline__ void mbar_init(unsigned mbar, unsigned cnt) {
    asm volatile("mbarrier.init.shared.b64 [%0], %1;" :: "r"(mbar), "r"(cnt) : "memory");
}

__device__ __forceinline__ void mbar_expect_tx(unsigned mbar, unsigned bytes) {
    asm volatile("mbarrier.arrive.expect_tx.shared.b64 _, [%0], %1;"
                 :: "r"(mbar), "r"(bytes) : "memory");
}

__device__ __forceinline__ void mbar_wait(unsigned mbar, unsigned phase) {
    asm volatile(
        "{\n\t"
        ".reg .pred P;\n\t"
        "WL_%=: \n\t"
        "mbarrier.try_wait.parity.shared.b64 P, [%0], %1, 0x989680;\n\t"
        "@P bra WD_%=;\n\t"
        "bra WL_%=;\n\t"
        "WD_%=: \n\t"
        "}"
        :: "r"(mbar), "r"(phase) : "memory");
}

__device__ __forceinline__ void bulk_g2s(unsigned dst, const void* src,
                                         unsigned bytes, unsigned mbar) {
    asm volatile(
        "cp.async.bulk.shared::cluster.global.mbarrier::complete_tx::bytes "
        "[%0], [%1], %2, [%3];"
        :: "r"(dst), "l"(src), "r"(bytes), "r"(mbar) : "memory");
}

// ---------------- per-layer prep: pack Wh (fp16), zero state, reset barrier -
__global__ void __launch_bounds__(256)
prep_kernel(const float* __restrict__ Wh)
{
    int idx = blockIdx.x * blockDim.x + threadIdx.x;  // 0 .. NCTA*32*HID-1
    if (idx == 0) { g_bar_count = 0; g_bar_epoch = 0; }
    if (idx < (16 * CHWH) / 2) { ((unsigned*)g_hbitsA)[idx] = 0u; }
    int cta = idx >> 15;
    int k   = (idx >> 5) & (HID - 1);
    int c   = idx & 31;
    float v = Wh[(size_t)k * GATES + (c >> 3) * HID + cta * 8 + (c & 7)];
    g_whpack[((size_t)cta << 15) + (size_t)c * HID + k] = __float2half_rn(v);
}

// ---------------- xproj GEMM (fp16): C = A @ Wx + bias ---------------------
// A [m][K] fp32 -> staged fp16. Wx [k][n] fp32 -> staged fp16, B fragments
// via ldmatrix.trans. BM=128, BN=128, BK=32; 8 warps (2m x 4n), fp32 accum.
__global__ void __launch_bounds__(256)
xproj_gemm_kernel(const float* __restrict__ Aext, int use_hbuf,
                  const float* __restrict__ Wx, const float* __restrict__ bias, int K)
{
    const float* A = use_hbuf ? g_hbuf : Aext;

    __shared__ __half Ah[128][40];   // [m][k] stride 80B
    __shared__ __half Bh[32][136];   // [k][n] stride 272B

    const int bm = blockIdx.y, bn = blockIdx.x;
    const int tid = threadIdx.x;
    const int wid = tid >> 5, lane = tid & 31;
    const int wm = (wid >> 2) * 64;
    const int wn = (wid & 3) * 32;
    const int group = lane >> 2, tid4 = lane & 3;

    float acc[4][4][4];
#pragma unroll
    for (int i = 0; i < 4; i++)
#pragma unroll
        for (int j = 0; j < 4; j++)
#pragma unroll
            for (int k = 0; k < 4; k++) acc[i][j][k] = 0.0f;

    const float* Aptr = A + (size_t)(bm * 128) * K;
    const float* Bptr = Wx + (size_t)bn * 128;

    // ldmatrix lane addresses
    const unsigned ahb = (unsigned)__cvta_generic_to_shared(&Ah[0][0]);
    const unsigned bhb = (unsigned)__cvta_generic_to_shared(&Bh[0][0]);
    // A: rows m = wm + (lane&15), k-octet (lane>>4)
    const unsigned aAddr = ahb + (unsigned)(((wm + (lane & 15)) * 40 + ((lane >> 4) * 8)) * 2);
    // B (trans): rows k = lane&15, n base = wn
    const unsigned bAddr = bhb + (unsigned)(((lane & 15) * 136 + wn) * 2);

    for (int k0 = 0; k0 < K; k0 += 32) {
        // stage A: 128 x 32 fp32 -> fp16
#pragma unroll
        for (int j = 0; j < 4; j++) {
            int idx = tid + j * 256;
            int r = idx >> 3, c4 = idx & 7;
            float4 v = *(const float4*)(Aptr + (size_t)r * K + k0 + c4 * 4);
            __half2* dst = (__half2*)&Ah[r][c4 * 4];
            dst[0] = __floats2half2_rn(v.x, v.y);
            dst[1] = __floats2half2_rn(v.z, v.w);
        }
        // stage B: 32 x 128 fp32 -> fp16
#pragma unroll
        for (int j = 0; j < 4; j++) {
            int idx = tid + j * 256;
            int r = idx >> 5, c4 = idx & 31;
            float4 v = *(const float4*)(Bptr + (size_t)(k0 + r) * GATES + c4 * 4);
            __half2* dst = (__half2*)&Bh[r][c4 * 4];
            dst[0] = __floats2half2_rn(v.x, v.y);
            dst[1] = __floats2half2_rn(v.z, v.w);
        }
        __syncthreads();

#pragma unroll
        for (int ks = 0; ks < 2; ++ks) {
            unsigned a[4][4], b[4][2];
#pragma unroll
            for (int mf = 0; mf < 4; ++mf)
                ldsm_x4(a[mf][0], a[mf][1], a[mf][2], a[mf][3],
                        aAddr + (unsigned)(mf * 1280 + ks * 32));
#pragma unroll
            for (int nf = 0; nf < 4; ++nf)
                ldsm_x2t(b[nf][0], b[nf][1],
                         bAddr + (unsigned)(ks * 4352 + nf * 16));
#pragma unroll
            for (int mf = 0; mf < 4; ++mf)
#pragma unroll
                for (int nf = 0; nf < 4; ++nf)
                    mma_f16(acc[mf][nf], a[mf][0], a[mf][1], a[mf][2], a[mf][3],
                            b[nf][0], b[nf][1]);
        }
        __syncthreads();
    }

#pragma unroll
    for (int mf = 0; mf < 4; mf++) {
#pragma unroll
        for (int nf = 0; nf < 4; nf++) {
            int col = bn * 128 + wn + nf * 8 + 2 * tid4;
            float bv0 = bias[col], bv1 = bias[col + 1];
#pragma unroll
            for (int r = 0; r < 2; r++) {
                int m = bm * 128 + wm + mf * 16 + group + r * 8;
                int bidx = m >> 10;
                int tt = m & (TLEN - 1);
                float2 v;
                v.x = acc[mf][nf][2 * r + 0] + bv0;
                v.y = acc[mf][nf][2 * r + 1] + bv1;
                *(float2*)&g_xproj[((size_t)tt * BATCH + bidx) * GATES + col] = v;
            }
        }
    }
}

// ---------------- persistent LSTM layer kernel (fp16 recurrence GEMM) ------
// 128 CTAs x 256 threads. CTA owns hidden units [j0, j0+8) (32 gate cols).
// Wh slice resident in smem (fp16). h staged via TMA bulk copies, double
// buffered, 2 chunks per k-half per buffer (4 iterations of k=128).
struct LayerSmem {
    __half Bs[32][1032];          // resident Wh slice [col][k]   (66,048 B)
    __half As[2][2][2][64][72];   // [buf][khalf][sub][b][k]      (73,728 B)
    float zsm[2][4][64][9];       // [khalf][gate][b][jj]         (18,432 B)
    unsigned long long mbar[2];   // TMA completion barriers
};

__global__ void __launch_bounds__(256, 1)
lstm_layer_kernel(float* __restrict__ dout_ext, int last)
{
    extern __shared__ char dynbuf[];
    LayerSmem& sm = *reinterpret_cast<LayerSmem*>(dynbuf);

    float* dout = last ? dout_ext : g_hbuf;
    const int tid = threadIdx.x;
    const int wid = tid >> 5, lane = tid & 31;
    const int g = wid & 3;            // gate
    const int hl_w = wid >> 2;        // K-half (0: k<512, 1: k>=512)
    const int j0 = blockIdx.x * 8;
    const int group = lane >> 2, tid4 = lane & 3;
    const __half* wp = g_whpack + ((size_t)blockIdx.x << 15);  // [32][1024] halves

    const unsigned mb0 = (unsigned)__cvta_generic_to_shared(&sm.mbar[0]);
    const unsigned mb1 = (unsigned)__cvta_generic_to_shared(&sm.mbar[1]);
    const unsigned asbase = (unsigned)__cvta_generic_to_shared(&sm.As[0][0][0][0][0]);
    const unsigned bsbase = (unsigned)__cvta_generic_to_shared(&sm.Bs[0][0]);

    // ldmatrix per-lane addresses (byte offsets):
    // A: row = lane&15 (stride 144B), k-octet select = lane>>4 (+16B)
    const unsigned aoff = (lane & 15) * 144u + ((lane >> 4) << 4);
    const unsigned abase0 = asbase + (unsigned)(hl_w * (2 * CHB)) + aoff;     // buf 0
    const unsigned abase1 = abase0 + 4u * CHB;                                 // buf 1
    // B: row = g*8 + (lane&7) (stride 2064B), khalf offset 1024B, k-octet (lane>>3)&1
    const unsigned bbase = bsbase + (unsigned)((g * 8 + (lane & 7)) * 2064)
                           + (unsigned)(hl_w * 1024) + ((((unsigned)lane >> 3) & 1u) << 4);

    if (tid == 0) {
        mbar_init(mb0, 1);
        mbar_init(mb1, 1);
        asm volatile("fence.proxy.async.shared::cta;" ::: "memory");
    }

    // ---- load resident Wh slice once: 32 cols x 1024 k halves ----
#pragma unroll
    for (int j = 0; j < 16; ++j) {
        int idx = tid + j * 256;      // 0..4095 uint4s (16B = 8 halves)
        int c = idx >> 7;
        int k16 = idx & 127;
        uint4 v = *(const uint4*)((const char*)(wp + (size_t)c * HID) + k16 * 16);
        *(uint4*)((char*)&sm.Bs[c][0] + k16 * 16) = v;
    }

    // cell state in registers: thread handles (b,jj) pairs idx=tid, tid+256
    float creg[2] = {0.0f, 0.0f};
    unsigned ph0 = 0, ph1 = 0;

    __syncthreads();

    for (int t = 0; t < TLEN; ++t) {
        const __half* hprev = (t & 1) ? g_hbitsB : g_hbitsA;
        __half* hnext = (t & 1) ? g_hbitsA : g_hbitsB;

        // prefetch xproj for this step's epilogue (hides DRAM latency)
        const float* xp = g_xproj + (size_t)t * BATCH * GATES;
        float xpv[2][4];
#pragma unroll
        for (int e = 0; e < 2; ++e) {
            int idx = tid + e * 256;
            int b = idx >> 3, jj = idx & 7;
            const float* xpb = xp + (size_t)b * GATES + j0 + jj;
#pragma unroll
            for (int gg = 0; gg < 4; ++gg) xpv[e][gg] = __ldg(xpb + gg * HID);
        }

        // stage superchunk 0 into buf 0: khalf0 <- chunks 0,1; khalf1 <- 8,9
        if (tid == 0) {
            mbar_expect_tx(mb0, 4 * CHB);
            bulk_g2s(asbase, hprev, 2 * CHB, mb0);
            bulk_g2s(asbase + 2 * CHB, hprev + 8 * CHWH, 2 * CHB, mb0);
        }

        float acc[4][4];
#pragma unroll
        for (int i = 0; i < 4; i++)
#pragma unroll
            for (int k = 0; k < 4; k++) acc[i][k] = 0.0f;

#pragma unroll 1
        for (int i = 0; i < 4; ++i) {
            const int buf = i & 1;
            // wait for this buffer's TMA completion
            if (buf == 0) { mbar_wait(mb0, ph0); ph0 ^= 1; }
            else          { mbar_wait(mb1, ph1); ph1 ^= 1; }

            // issue next superchunk into the other buffer
            if (tid == 0 && i < 3) {
                const int nb = (i + 1) & 1;
                const unsigned m = nb ? mb1 : mb0;
                const unsigned d = asbase + (unsigned)nb * (4 * CHB);
                mbar_expect_tx(m, 4 * CHB);
                bulk_g2s(d, hprev + (size_t)(2 * (i + 1)) * CHWH, 2 * CHB, m);
                bulk_g2s(d + 2 * CHB, hprev + (size_t)(8 + 2 * (i + 1)) * CHWH, 2 * CHB, m);
            }

            const unsigned ab = buf ? abase1 : abase0;
#pragma unroll
            for (int sub = 0; sub < 2; ++sub) {
                const unsigned kgb = (unsigned)(i * 256 + sub * 128);  // B k-bytes
                const unsigned asub = ab + (unsigned)sub * CHB;
#pragma unroll
                for (int kk = 0; kk < 4; ++kk) {
                    const unsigned kc = (unsigned)kk * 32u;
                    unsigned b0, b1;
                    ldsm_x2(b0, b1, bbase + kgb + kc);
#pragma unroll
                    for (int mf = 0; mf < 4; ++mf) {
                        unsigned a0, a1, a2, a3;
                        ldsm_x4(a0, a1, a2, a3, asub + (unsigned)mf * 2304u + kc);
                        mma_f16(acc[mf], a0, a1, a2, a3, b0, b1);
                    }
                }
            }
            __syncthreads();  // mma on buf done -> buf free for next TMA
        }

        // stash z fragments
#pragma unroll
        for (int mf = 0; mf < 4; ++mf) {
            int m = mf * 16 + group, n = 2 * tid4;
            sm.zsm[hl_w][g][m][n]     = acc[mf][0];
            sm.zsm[hl_w][g][m][n + 1] = acc[mf][1];
            sm.zsm[hl_w][g][m + 8][n]     = acc[mf][2];
            sm.zsm[hl_w][g][m + 8][n + 1] = acc[mf][3];
        }
        __syncthreads();

        // elementwise gates: 64 b x 8 jj = 512 / 256 thr = 2 each; c in regs
        const int hchunk = j0 >> 6;           // this CTA's cols live in one chunk
#pragma unroll
        for (int e = 0; e < 2; ++e) {
            int idx = tid + e * 256;
            int b = idx >> 3, jj = idx & 7;
            int col = j0 + jj;
            float zi = sm.zsm[0][0][b][jj] + sm.zsm[1][0][b][jj] + xpv[e][0];
            float zf = sm.zsm[0][1][b][jj] + sm.zsm[1][1][b][jj] + xpv[e][1];
            float zg = sm.zsm[0][2][b][jj] + sm.zsm[1][2][b][jj] + xpv[e][2];
            float zo = sm.zsm[0][3][b][jj] + sm.zsm[1][3][b][jj] + xpv[e][3];
            float i_ = sigmoidf_fast(zi);
            float f_ = sigmoidf_fast(zf);
            float gg_ = tanhf(zg);
            float o_ = sigmoidf_fast(zo);
            float c_ = f_ * creg[e] + i_ * gg_;
            creg[e] = c_;
            float h_ = o_ * tanhf(c_);
            hnext[hchunk * CHWH + b * 72 + (col & 63)] = __float2half_rn(h_);
            dout[(size_t)b * TLEN * HID + (size_t)t * HID + col] = h_;
        }
        __syncthreads();

        // ---- grid barrier (monotonic epoch) ----
        if (tid == 0) {
            asm volatile("fence.proxy.async;" ::: "memory");
            __threadfence();
            unsigned prev = atomicAdd(&g_bar_count, 1u);
            if (prev == NCTA - 1) {
                g_bar_count = 0;
                __threadfence();
                atomicExch(&g_bar_epoch, (unsigned)(t + 1));
            } else {
                volatile unsigned* ep = &g_bar_epoch;
                while (*ep < (unsigned)(t + 1)) { }
                __threadfence();
            }
        }
        __syncthreads();
    }
}

// ---------------- launch ----------------
extern "C" void kernel_launch(void* const* d_in, const int* in_sizes, int n_in,
                              void* d_out, int out_size)
{
    (void)in_sizes; (void)n_in; (void)out_size;
    const float* xs = (const float*)d_in[0];
    const float* Wx[3] = {(const float*)d_in[1], (const float*)d_in[4], (const float*)d_in[7]};
    const float* Wh[3] = {(const float*)d_in[2], (const float*)d_in[5], (const float*)d_in[8]};
    const float* bb[3] = {(const float*)d_in[3], (const float*)d_in[6], (const float*)d_in[9]};
    float* out = (float*)d_out;

    static int smem_set = 0;
    int smem_bytes = (int)sizeof(LayerSmem);
    if (!smem_set) {
        cudaFuncSetAttribute(lstm_layer_kernel,
                             cudaFuncAttributeMaxDynamicSharedMemorySize, smem_bytes);
        smem_set = 1;
    }

    for (int l = 0; l < 3; l++) {
        int K = (l == 0) ? FEAT : HID;
        prep_kernel<<<(NCTA * 32 * HID) / 256, 256>>>(Wh[l]);
        dim3 ggrid(GATES / 128, (BATCH * TLEN) / 128);
        xproj_gemm_kernel<<<ggrid, 256>>>(l == 0 ? xs : nullptr, l > 0 ? 1 : 0,
                                          Wx[l], bb[l], K);
        lstm_layer_kernel<<<NCTA, 256, smem_bytes>>>(out, (l == 2) ? 1 : 0);
    }
}